// round 5
// baseline (speedup 1.0000x reference)
#include <cuda_runtime.h>

// ROIAlignRotated3D, fixed shapes:
//   input: (B=2, C=128, 64,64,64) f32, rois: (N=128, 8) f32, scalar spatial_scale
//   output: (N, C, 7, 7, 7) f32
//
// Separable z-line formulation. Per block = (roi, 16-channel group), 224 threads
// (7 warps). Per channel:
//   Phase 1: warp w owns xy-bins (w, 0..6). For each of its 4 xy-samples it
//     reads 4 corner z-rows with lane<->zv contiguous loads (128B, 4 sectors,
//     predicated to the roi's z-extent <= 32) and accumulates the xy-bilinear
//     into shared C[binxy][zv] (xy weights + xy valid folded in).
//   Phase 2: thread per bin: out = sum_l  vz*(hz*C[q][z0] + lz*C[q][z1]) / 8.
// All z indices/weights are roi-uniform and precomputed once per block.

#define NS     14          // 7 * SR
#define BINS   343
#define CH     128
#define G      16          // channels per block
#define VOLSZ  (64*64*64)
#define NT     224         // 7 warps

__global__ __launch_bounds__(NT)
void roi_align_rot3d_sep_kernel(const float* __restrict__ input,
                                const float* __restrict__ rois,
                                const float* __restrict__ ssp,
                                float* __restrict__ out)
{
    __shared__ float  s_roi[8];
    __shared__ int4   s_pi[196];    // base00, dx_off, dy_off, 0
    __shared__ float4 s_pw[196];    // w00, w10, w01, w11  (xy-valid folded in)
    __shared__ int    s_zi0[14], s_zi1[14];   // z corner indices rel. zbase
    __shared__ float  s_zwh[14], s_zwl[14];   // hz*vz, lz*vz
    __shared__ float  s_C[49][33];            // padded stride

    const int n   = blockIdx.x;        // roi (fast-varying -> L2 reuse)
    const int c0  = blockIdx.y * G;
    const int tid = threadIdx.x;

    if (tid < 8) s_roi[tid] = rois[n * 8 + tid];
    __syncthreads();

    const float ss = __ldg(ssp);
    const int   b  = (int)s_roi[0];
    const float cx = s_roi[1] * ss, cy = s_roi[2] * ss, cz = s_roi[3] * ss;
    const float sx = s_roi[4] * ss, sy = s_roi[5] * ss, sz = s_roi[6] * ss;
    const float th = s_roi[7];

    // roi-uniform z base (every thread computes identically)
    const float dzs    = sz * (1.0f / NS);
    const float zfirst = fminf(fmaxf(cz - 0.5f * sz + 0.5f * dzs, 0.0f), 63.0f);
    const int   zbase  = (int)floorf(zfirst);

    // ---- per-block precompute ----
    if (tid < 196) {
        float ct, st;
        sincosf(th, &st, &ct);
        const int i = tid / NS;          // x-sample
        const int j = tid % NS;          // y-sample
        const float ox = -0.5f * sx + ((float)i + 0.5f) * (sx * (1.0f / NS));
        const float oy = -0.5f * sy + ((float)j + 0.5f) * (sy * (1.0f / NS));
        float x = ct * ox - st * oy + cx;
        float y = st * ox + ct * oy + cy;
        const float v = (x > -1.0f && x < 64.0f && y > -1.0f && y < 64.0f) ? 1.0f : 0.0f;
        x = fminf(fmaxf(x, 0.0f), 63.0f);
        y = fminf(fmaxf(y, 0.0f), 63.0f);
        const int x0 = (int)floorf(x);
        const int y0 = (int)floorf(y);
        const int x1 = min(x0 + 1, 63);
        const int y1 = min(y0 + 1, 63);
        const float lx = x - (float)x0, hx = 1.0f - lx;
        const float ly = y - (float)y0, hy = 1.0f - ly;
        s_pi[tid] = make_int4(x0 * 4096 + y0 * 64, (x1 - x0) * 4096, (y1 - y0) * 64, 0);
        s_pw[tid] = make_float4(hx * hy * v, lx * hy * v, hx * ly * v, lx * ly * v);
    }
    if (tid < 14) {
        float z = cz - 0.5f * sz + ((float)tid + 0.5f) * dzs;
        const float v = (z > -1.0f && z < 64.0f) ? 1.0f : 0.0f;
        z = fminf(fmaxf(z, 0.0f), 63.0f);
        const int z0 = (int)floorf(z);
        const int z1 = min(z0 + 1, 63);
        const float lz = z - (float)z0;
        s_zi0[tid] = z0 - zbase;          // in [0, 31]
        s_zi1[tid] = z1 - zbase;
        s_zwh[tid] = (1.0f - lz) * v;
        s_zwl[tid] = lz * v;
    }
    __syncthreads();

    const int wid  = tid >> 5;
    const int lane = tid & 31;
    const int zext = s_zi1[13] + 1;               // <= 32
    const int zoff = min(zbase + lane, 63);       // contiguous lane<->zv

    // Hoist per-thread phase-2 z tables into registers (roi-uniform per bin).
    // Thread handles bins tid and tid+224.
    const int b0 = tid;
    const int b1 = tid + NT;
    int   q0, a00, a01, a10, a11;
    float wa0h, wa0l, wa1h, wa1l;
    int   q1 = 0, c00 = 0, c01 = 0, c10 = 0, c11 = 0;
    float wb0h = 0.f, wb0l = 0.f, wb1h = 0.f, wb1l = 0.f;
    {
        const int ix = b0 / 49, rem = b0 % 49, iy = rem / 7, iz = rem % 7;
        q0 = ix * 7 + iy;
        a00 = s_zi0[2 * iz];     a01 = s_zi1[2 * iz];
        a10 = s_zi0[2 * iz + 1]; a11 = s_zi1[2 * iz + 1];
        wa0h = s_zwh[2 * iz];     wa0l = s_zwl[2 * iz];
        wa1h = s_zwh[2 * iz + 1]; wa1l = s_zwl[2 * iz + 1];
    }
    if (b1 < BINS) {
        const int ix = b1 / 49, rem = b1 % 49, iy = rem / 7, iz = rem % 7;
        q1 = ix * 7 + iy;
        c00 = s_zi0[2 * iz];     c01 = s_zi1[2 * iz];
        c10 = s_zi0[2 * iz + 1]; c11 = s_zi1[2 * iz + 1];
        wb0h = s_zwh[2 * iz];     wb0l = s_zwl[2 * iz];
        wb1h = s_zwh[2 * iz + 1]; wb1l = s_zwl[2 * iz + 1];
    }

    const float* volbase = input + ((size_t)b * CH + (size_t)c0) * (size_t)VOLSZ;
    float*       outbase = out + ((size_t)n * CH + (size_t)c0) * BINS;

    for (int c = 0; c < G; ++c) {
        const float* __restrict__ vol = volbase + (size_t)c * VOLSZ;

        // ---- phase 1: build C[binxy][zv] ----
        if (lane < zext) {
            for (int t = 0; t < 7; ++t) {
                const int q = wid * 7 + t;   // qx = wid, qy = t
                float acc = 0.0f;
                #pragma unroll
                for (int jj = 0; jj < 2; ++jj) {
                    #pragma unroll
                    for (int kk = 0; kk < 2; ++kk) {
                        const int p = (2 * wid + jj) * NS + (2 * t + kk);
                        const int4   pi = s_pi[p];
                        const float4 pw = s_pw[p];
                        const float* r  = vol + pi.x + zoff;
                        const float v00 = r[0];
                        const float v10 = r[pi.y];
                        const float v01 = r[pi.z];
                        const float v11 = r[pi.y + pi.z];
                        acc += pw.x * v00 + pw.y * v10 + pw.z * v01 + pw.w * v11;
                    }
                }
                s_C[q][lane] = acc;
            }
        }
        __syncthreads();

        // ---- phase 2: z-interp + write ----
        {
            float* outc = outbase + (size_t)c * BINS;
            {
                float a = wa0h * s_C[q0][a00] + wa0l * s_C[q0][a01]
                        + wa1h * s_C[q0][a10] + wa1l * s_C[q0][a11];
                outc[b0] = a * 0.125f;
            }
            if (b1 < BINS) {
                float a = wb0h * s_C[q1][c00] + wb0l * s_C[q1][c01]
                        + wb1h * s_C[q1][c10] + wb1l * s_C[q1][c11];
                outc[b1] = a * 0.125f;
            }
        }
        __syncthreads();
    }
}

extern "C" void kernel_launch(void* const* d_in, const int* in_sizes, int n_in,
                              void* d_out, int out_size)
{
    const float* input = (const float*)d_in[0];
    const float* rois  = (const float*)d_in[1];
    const float* ss    = (const float*)d_in[2];
    float* out         = (float*)d_out;

    const int N = in_sizes[1] / 8;

    dim3 grid(N, CH / G, 1);
    roi_align_rot3d_sep_kernel<<<grid, NT>>>(input, rois, ss, out);
}

// round 8
// speedup vs baseline: 1.4406x; 1.4406x over previous
#include <cuda_runtime.h>

// ROIAlignRotated3D, fixed shapes:
//   input: (B=2, C=128, 64,64,64) f32, rois: (N=128, 8) f32, scalar spatial_scale
//   output: (N, C, 7, 7, 7) f32
//
// Separable z-line formulation, warp-independent version.
// Block = (roi, 8-channel group), 224 threads (7 warps). Warp w owns output
// column ix=w (49 bins). Channels processed in pairs with no block-wide sync
// inside the loop (phase-2 reads only the warp's own s_C rows -> __syncwarp).
//   Phase 1: warp's 7 xy-columns x 4 xy-samples; lanes = contiguous z voxels
//     (128B rows, 4 sectors), xy-bilinear folded into s_C[q][zv] for 2
//     channels at once (32 independent LDGs in flight).
//   Phase 2: lane -> local bins {lane, lane+32} of the warp's 49; z-interp
//     from s_C via roi-uniform per-lane register tables; coalesced writes.

#define NS     14
#define BINS   343
#define CH     128
#define G      8           // channels per block
#define VOLSZ  (64*64*64)
#define NT     224         // 7 warps

__global__ __launch_bounds__(NT)
void roi_align_rot3d_wsep_kernel(const float* __restrict__ input,
                                 const float* __restrict__ rois,
                                 const float* __restrict__ ssp,
                                 float* __restrict__ out)
{
    __shared__ float  s_roi[8];
    __shared__ int4   s_pi[196];              // base00, dx_off, dy_off, 0
    __shared__ float4 s_pw[196];              // w00, w10, w01, w11 (xy-valid folded)
    __shared__ int    s_zi0[14], s_zi1[14];   // z corner indices rel. zbase
    __shared__ float  s_zwh[14], s_zwl[14];   // hz*vz, lz*vz
    __shared__ float  s_C0[49][33];           // z-line tables, 2 channels
    __shared__ float  s_C1[49][33];

    const int n   = blockIdx.x;        // roi fast-varying -> L2 reuse
    const int c0  = blockIdx.y * G;
    const int tid = threadIdx.x;

    if (tid < 8) s_roi[tid] = rois[n * 8 + tid];
    __syncthreads();

    const float ss = __ldg(ssp);
    const int   b  = (int)s_roi[0];
    const float cx = s_roi[1] * ss, cy = s_roi[2] * ss, cz = s_roi[3] * ss;
    const float sx = s_roi[4] * ss, sy = s_roi[5] * ss, sz = s_roi[6] * ss;
    const float th = s_roi[7];

    const float dzs    = sz * (1.0f / NS);
    const float zfirst = fminf(fmaxf(cz - 0.5f * sz + 0.5f * dzs, 0.0f), 63.0f);
    const int   zbase  = (int)floorf(zfirst);

    // ---- per-block precompute (once) ----
    if (tid < 196) {
        float ct, st;
        sincosf(th, &st, &ct);
        const int i = tid / NS;          // x-sample
        const int j = tid % NS;          // y-sample
        const float ox = -0.5f * sx + ((float)i + 0.5f) * (sx * (1.0f / NS));
        const float oy = -0.5f * sy + ((float)j + 0.5f) * (sy * (1.0f / NS));
        float x = ct * ox - st * oy + cx;
        float y = st * ox + ct * oy + cy;
        const float v = (x > -1.0f && x < 64.0f && y > -1.0f && y < 64.0f) ? 1.0f : 0.0f;
        x = fminf(fmaxf(x, 0.0f), 63.0f);
        y = fminf(fmaxf(y, 0.0f), 63.0f);
        const int x0 = (int)floorf(x);
        const int y0 = (int)floorf(y);
        const int x1 = min(x0 + 1, 63);
        const int y1 = min(y0 + 1, 63);
        const float lx = x - (float)x0, hx = 1.0f - lx;
        const float ly = y - (float)y0, hy = 1.0f - ly;
        s_pi[tid] = make_int4(x0 * 4096 + y0 * 64, (x1 - x0) * 4096, (y1 - y0) * 64, 0);
        s_pw[tid] = make_float4(hx * hy * v, lx * hy * v, hx * ly * v, lx * ly * v);
    }
    if (tid < 14) {
        float z = cz - 0.5f * sz + ((float)tid + 0.5f) * dzs;
        const float v = (z > -1.0f && z < 64.0f) ? 1.0f : 0.0f;
        z = fminf(fmaxf(z, 0.0f), 63.0f);
        const int z0 = (int)floorf(z);
        const int z1 = min(z0 + 1, 63);
        const float lz = z - (float)z0;
        s_zi0[tid] = z0 - zbase;          // in [0, 31]
        s_zi1[tid] = z1 - zbase;
        s_zwh[tid] = (1.0f - lz) * v;
        s_zwl[tid] = lz * v;
    }
    __syncthreads();

    const int wid  = tid >> 5;
    const int lane = tid & 31;
    const int zext = s_zi1[13] + 1;            // <= 32
    const int zoff = zbase + lane;             // contiguous lane<->zv (used when lane<zext)

    // ---- per-lane phase-2 register tables (roi-uniform) ----
    // Warp w's 49 bins are (ix=w, iy=bl/7, iz=bl%7); lane handles bl0=lane, bl1=lane+32.
    const int bl0 = lane;                      // always < 49
    const int iy0 = bl0 / 7, iz0 = bl0 % 7;
    const int q0  = wid * 7 + iy0;
    const int a00 = s_zi0[2 * iz0],     a01 = s_zi1[2 * iz0];
    const int a10 = s_zi0[2 * iz0 + 1], a11 = s_zi1[2 * iz0 + 1];
    const float wa0h = s_zwh[2 * iz0],     wa0l = s_zwl[2 * iz0];
    const float wa1h = s_zwh[2 * iz0 + 1], wa1l = s_zwl[2 * iz0 + 1];

    const int  bl1   = lane + 32;
    const bool has1  = (bl1 < 49);             // lane < 17
    const int  iy1   = has1 ? bl1 / 7 : 0;
    const int  iz1   = has1 ? bl1 % 7 : 0;
    const int  q1    = wid * 7 + iy1;
    const int  d00 = s_zi0[2 * iz1],     d01 = s_zi1[2 * iz1];
    const int  d10 = s_zi0[2 * iz1 + 1], d11 = s_zi1[2 * iz1 + 1];
    const float wb0h = s_zwh[2 * iz1],     wb0l = s_zwl[2 * iz1];
    const float wb1h = s_zwh[2 * iz1 + 1], wb1l = s_zwl[2 * iz1 + 1];

    const float* volbase = input + ((size_t)b * CH + (size_t)c0) * (size_t)VOLSZ;
    float*       outbase = out + ((size_t)n * CH + (size_t)c0) * BINS;

    for (int c = 0; c < G; c += 2) {
        const float* __restrict__ vol0 = volbase + (size_t)c * VOLSZ;
        const float* __restrict__ vol1 = vol0 + VOLSZ;

        // ---- phase 1: build z-line tables for 2 channels ----
        if (lane < zext) {
            #pragma unroll
            for (int t = 0; t < 7; ++t) {
                const int q = wid * 7 + t;
                float acc0 = 0.0f, acc1 = 0.0f;
                #pragma unroll
                for (int jj = 0; jj < 2; ++jj) {
                    #pragma unroll
                    for (int kk = 0; kk < 2; ++kk) {
                        const int p = (2 * wid + jj) * NS + (2 * t + kk);
                        const int4   pi = s_pi[p];
                        const float4 pw = s_pw[p];
                        const float* r0 = vol0 + pi.x + zoff;
                        const float* r1 = vol1 + pi.x + zoff;
                        const float a00v = r0[0];
                        const float b00v = r1[0];
                        const float a10v = r0[pi.y];
                        const float b10v = r1[pi.y];
                        const float a01v = r0[pi.z];
                        const float b01v = r1[pi.z];
                        const float a11v = r0[pi.y + pi.z];
                        const float b11v = r1[pi.y + pi.z];
                        acc0 = fmaf(pw.x, a00v, acc0);
                        acc1 = fmaf(pw.x, b00v, acc1);
                        acc0 = fmaf(pw.y, a10v, acc0);
                        acc1 = fmaf(pw.y, b10v, acc1);
                        acc0 = fmaf(pw.z, a01v, acc0);
                        acc1 = fmaf(pw.z, b01v, acc1);
                        acc0 = fmaf(pw.w, a11v, acc0);
                        acc1 = fmaf(pw.w, b11v, acc1);
                    }
                }
                s_C0[q][lane] = acc0;
                s_C1[q][lane] = acc1;
            }
        }
        __syncwarp();

        // ---- phase 2: warp-local z-interp + coalesced writes ----
        {
            float* outc0 = outbase + (size_t)c * BINS;
            float* outc1 = outc0 + BINS;
            const int gb0 = wid * 49 + bl0;
            {
                float r0 = wa0h * s_C0[q0][a00] + wa0l * s_C0[q0][a01]
                         + wa1h * s_C0[q0][a10] + wa1l * s_C0[q0][a11];
                float r1 = wa0h * s_C1[q0][a00] + wa0l * s_C1[q0][a01]
                         + wa1h * s_C1[q0][a10] + wa1l * s_C1[q0][a11];
                outc0[gb0] = r0 * 0.125f;
                outc1[gb0] = r1 * 0.125f;
            }
            if (has1) {
                const int gb1 = wid * 49 + bl1;
                float r0 = wb0h * s_C0[q1][d00] + wb0l * s_C0[q1][d01]
                         + wb1h * s_C0[q1][d10] + wb1l * s_C0[q1][d11];
                float r1 = wb0h * s_C1[q1][d00] + wb0l * s_C1[q1][d01]
                         + wb1h * s_C1[q1][d10] + wb1l * s_C1[q1][d11];
                outc0[gb1] = r0 * 0.125f;
                outc1[gb1] = r1 * 0.125f;
            }
        }
        __syncwarp();   // protect s_C against next iteration's overwrite
    }
}

extern "C" void kernel_launch(void* const* d_in, const int* in_sizes, int n_in,
                              void* d_out, int out_size)
{
    const float* input = (const float*)d_in[0];
    const float* rois  = (const float*)d_in[1];
    const float* ss    = (const float*)d_in[2];
    float* out         = (float*)d_out;

    const int N = in_sizes[1] / 8;

    dim3 grid(N, CH / G, 1);
    roi_align_rot3d_wsep_kernel<<<grid, NT>>>(input, rois, ss, out);
}